// round 16
// baseline (speedup 1.0000x reference)
#include <cuda_runtime.h>
#include <cuda_fp16.h>
#include <math.h>
#include <stdint.h>

#define B_SIZE 32768
#define E_DIM  256
#define NF     512
#define NWIN   6
#define BN_EPS 1e-5
#define KCAT   1792   // 512 (type0) + 512 (type1) + 768 (typeH)
#define NRV    50000

// ---------------- scratch (static device arrays) ----------------
__device__ __half g_out1h[(size_t)2 * B_SIZE * NF];  // windows 0,1 (with bias), fp16
__device__ float  g_H    [(size_t)B_SIZE * NF];      // H + b2 (fp32)
__device__ __half g_out2h[(size_t)4 * B_SIZE * NF];  // windows 2..5 complete (H + p2), fp16
__device__ float  g_sumf[NWIN * NF];
__device__ float  g_sqf [NWIN * NF];
__device__ float  g_scale[NWIN * NF];
__device__ float  g_shift[NWIN * NF];

// fp16 tables / weights
__device__ __half g_er[(size_t)NRV * E_DIM];
__device__ __half g_ev[(size_t)NRV * E_DIM];
__device__ __half g_w_h[(size_t)NF * KCAT];

// ---------------- helpers ----------------
__device__ __forceinline__ uint32_t smem_u32(const void* p) {
    uint32_t a;
    asm("{ .reg .u64 t; cvta.to.shared.u64 t, %1; cvt.u32.u64 %0, t; }" : "=r"(a) : "l"(p));
    return a;
}
__device__ __forceinline__ void cp16(uint32_t dst, const void* src) {
    asm volatile("cp.async.cg.shared.global [%0], [%1], 16;" :: "r"(dst), "l"(src));
}
__device__ __forceinline__ void ldsm4(uint32_t& r0, uint32_t& r1, uint32_t& r2, uint32_t& r3,
                                      uint32_t addr) {
    asm volatile("ldmatrix.sync.aligned.m8n8.x4.shared.b16 {%0,%1,%2,%3}, [%4];"
                 : "=r"(r0), "=r"(r1), "=r"(r2), "=r"(r3) : "r"(addr));
}
__device__ __forceinline__ void mma16816(float* d, const uint32_t* a, uint32_t b0, uint32_t b1) {
    asm volatile(
        "mma.sync.aligned.m16n8k16.row.col.f32.f16.f16.f32 "
        "{%0,%1,%2,%3}, {%4,%5,%6,%7}, {%8,%9}, {%0,%1,%2,%3};"
        : "+f"(d[0]), "+f"(d[1]), "+f"(d[2]), "+f"(d[3])
        : "r"(a[0]), "r"(a[1]), "r"(a[2]), "r"(a[3]), "r"(b0), "r"(b1));
}

// ---------------- prep kernels ----------------
__global__ void prep_tables_kernel(const float* __restrict__ er,
                                   const float* __restrict__ ev,
                                   int nre, int nve) {
    int total = nre + nve;
    for (int i = blockIdx.x * blockDim.x + threadIdx.x; i < total; i += gridDim.x * blockDim.x) {
        if (i < nre) g_er[i] = __float2half_rn(er[i]);
        else         g_ev[i - nre] = __float2half_rn(ev[i - nre]);
    }
}

__global__ void prep_w_kernel(const float* __restrict__ w1, const float* __restrict__ w2) {
    for (int i = blockIdx.x * blockDim.x + threadIdx.x; i < NF * KCAT; i += gridDim.x * blockDim.x) {
        if (i < NWIN * NF) { g_sumf[i] = 0.f; g_sqf[i] = 0.f; }
        int f = i / KCAT, k = i % KCAT;
        float v;
        if      (k < 256)  v = w1[((size_t)f * 2 + 0) * E_DIM + k];
        else if (k < 512)  v = w1[((size_t)f * 2 + 1) * E_DIM + (k - 256)];
        else if (k < 768)  v = w2[((size_t)f * 5 + 3) * E_DIM + (k - 512)];
        else if (k < 1024) v = w2[((size_t)f * 5 + 4) * E_DIM + (k - 768)];
        else if (k < 1280) v = w2[((size_t)f * 5 + 0) * E_DIM + (k - 1024)];
        else if (k < 1536) v = w2[((size_t)f * 5 + 1) * E_DIM + (k - 1280)];
        else               v = w2[((size_t)f * 5 + 2) * E_DIM + (k - 1536)];
        g_w_h[i] = __float2half_rn(v);
    }
}

// ---------------- GEMM kernel (mma.sync fp16, 64x64 warp tiles) ----------------
// phase 0: typeH, grid (256, 4)  -> writes g_H (= H + b2, fp32)
// phase 1: type0/1, grid (1536, 4) -> writes g_out1h / g_out2h(+H), computes BN stats
// block 128 (4 warps, 2x2; warp tile 64x64), 2 CTAs/SM, regs budget 256.
// smem: [0,512) bias; [512,1536) stats red; 2 stages of 32KB at 4096 (A 16K | B 16K).
// Single barrier per chunk: wait(c) ; sync ; issue(c+1) ; mma(c).
#define SM_RED      512
#define SM_STAGE0   4096
#define STAGE_BYTES 32768
#define SMEM_TOTAL  (SM_STAGE0 + 2 * STAGE_BYTES)

__global__ __launch_bounds__(128, 2) void gemm_kernel(
    const int phase,
    const int* __restrict__ x,
    const float* __restrict__ bvec)
{
    extern __shared__ char smem[];
    const uint32_t sb = smem_u32(smem);
    const int tid = threadIdx.x, wid = tid >> 5, lane = tid & 31;
    const int f0 = blockIdx.y * 128;

    int type, sub, b0, nch, kbase;
    if (phase == 0) { type = 2; sub = 0; b0 = blockIdx.x * 128; nch = 12; kbase = 1024; }
    else {
        const int tile = blockIdx.x;
        if (tile < 512) { type = 0; sub = tile >> 8;         b0 = (tile & 255) * 128;         nch = 8; kbase = 0; }
        else            { type = 1; sub = (tile - 512) >> 8; b0 = ((tile - 512) & 255) * 128; nch = 8; kbase = 512; }
    }

    {
        const float* bp = (type == 1) ? (const float*)0 : bvec;
        float* sbias = (float*)smem;
        sbias[tid] = bp ? bp[f0 + tid] : 0.0f;
        float* sred = (float*)(smem + SM_RED);
        sred[tid] = 0.0f;
        sred[tid + 128] = 0.0f;
    }

    // ---- gather setup: hoist per-cq index loads (row = tid, 0..127) ----
    const __half* Ath[3];
    int aidx[3] = {0, 0, 0};
    {
        int cols[3] = {0, 0, 0};
        int ncq;
        if (type == 0)      { cols[0] = 2 * sub + 1; Ath[0] = g_ev;
                              cols[1] = 0;           Ath[1] = g_er; ncq = 2; Ath[2] = g_er; }
        else if (type == 1) { cols[0] = 4 + 2 * sub; Ath[0] = g_er;
                              cols[1] = 5 + 2 * sub; Ath[1] = g_ev; ncq = 2; Ath[2] = g_ev; }
        else                { cols[0] = 1; Ath[0] = g_ev;
                              cols[1] = 0; Ath[1] = g_er;
                              cols[2] = 3; Ath[2] = g_ev; ncq = 3; }
        const int* xrow = x + (size_t)(b0 + tid) * 12;
#pragma unroll
        for (int q = 0; q < 3; q++)
            if (q < ncq) aidx[q] = __ldg(xrow + cols[q]);
    }

    auto issue_loads = [&](int cc) {
        const uint32_t tb = sb + SM_STAGE0 + (uint32_t)(cc & 1) * STAGE_BYTES;
        const uint32_t ro = (uint32_t)tid * 128;
        const uint32_t xr = (uint32_t)(tid & 7);
        // A row gather (full 128B row per thread)
        {
            const int cq = cc >> 2, e0 = (cc & 3) * 64;
            const char* sh = (const char*)(Ath[cq] + (size_t)aidx[cq] * E_DIM + e0);
#pragma unroll
            for (int g = 0; g < 8; g++) {
                const uint32_t so = ro + (uint32_t)((g ^ xr) * 16);
                cp16(tb + so, sh + g * 16);
            }
        }
        // B row (feature f0+tid)
        {
            const char* ph = (const char*)(g_w_h + (size_t)(f0 + tid) * KCAT + kbase + cc * 64);
#pragma unroll
            for (int g = 0; g < 8; g++) {
                const uint32_t so = ro + (uint32_t)((g ^ xr) * 16);
                cp16(tb + 16384 + so, ph + g * 16);
            }
        }
        asm volatile("cp.async.commit_group;" ::: "memory");
    };

    // ---- per-warp frag addressing (warp tile 64x64, warps 2x2) ----
    const int warpM = (wid & 1) * 64;
    const int warpN = (wid >> 1) * 64;
    uint32_t aOff[4], aXor[4];
#pragma unroll
    for (int mi = 0; mi < 4; mi++) {
        const int r = warpM + mi * 16 + (lane & 15);
        aOff[mi] = (uint32_t)r * 128;
        aXor[mi] = (uint32_t)(r & 7);
    }
    const uint32_t aSel = (uint32_t)((lane >> 4) & 1);
    uint32_t bOff[4], bXor[4];
#pragma unroll
    for (int p = 0; p < 4; p++) {
        const int r = warpN + p * 16 + (lane & 7) + (((lane >> 4) & 1) << 3);
        bOff[p] = (uint32_t)r * 128;
        bXor[p] = (uint32_t)(r & 7);
    }
    const uint32_t bSel = (uint32_t)((lane >> 3) & 1);

    float acc[4][8][4];
#pragma unroll
    for (int mi = 0; mi < 4; mi++)
#pragma unroll
        for (int ni = 0; ni < 8; ni++)
#pragma unroll
            for (int q = 0; q < 4; q++) acc[mi][ni][q] = 0.f;

    issue_loads(0);

    for (int c = 0; c < nch; c++) {
        asm volatile("cp.async.wait_group 0;" ::: "memory");
        __syncthreads();                     // chunk c ready; all warps done with c-1
        if (c + 1 < nch) issue_loads(c + 1); // other buffer last read in c-1 — safe

        const uint32_t tb = sb + SM_STAGE0 + (uint32_t)(c & 1) * STAGE_BYTES;
#pragma unroll
        for (int s = 0; s < 4; s++) {
            uint32_t fah[4][4], fb[4][4];
            const uint32_t blk = (uint32_t)(2 * s);
#pragma unroll
            for (int mi = 0; mi < 4; mi++) {
                const uint32_t ad = tb + aOff[mi] + (((blk + aSel) ^ aXor[mi]) * 16);
                ldsm4(fah[mi][0], fah[mi][1], fah[mi][2], fah[mi][3], ad);
            }
#pragma unroll
            for (int p = 0; p < 4; p++) {
                const uint32_t bd = tb + 16384 + bOff[p] + (((blk + bSel) ^ bXor[p]) * 16);
                ldsm4(fb[p][0], fb[p][1], fb[p][2], fb[p][3], bd);
            }
#pragma unroll
            for (int mi = 0; mi < 4; mi++)
#pragma unroll
                for (int ni = 0; ni < 8; ni++) {
                    const int p = ni >> 1, o = (ni & 1) * 2;
                    mma16816(acc[mi][ni], fah[mi], fb[p][o], fb[p][o + 1]);
                }
        }
    }

    // ---- epilogue ----
    const float* sbias = (const float*)smem;
    float* sred = (float*)(smem + SM_RED);
    const int lr = lane >> 2, lc = (lane & 3) * 2;
    const int nhalf = wid >> 1;

    if (type == 2) {
#pragma unroll
        for (int mi = 0; mi < 4; mi++) {
            const size_t r0 = (size_t)b0 + warpM + mi * 16 + lr;
#pragma unroll
            for (int ni = 0; ni < 8; ni++) {
                const int colLocal = warpN + ni * 8 + lc;
                const int f = f0 + colLocal;
                const float bi0 = sbias[colLocal], bi1 = sbias[colLocal + 1];
                float2 v0 = {acc[mi][ni][0] + bi0, acc[mi][ni][1] + bi1};
                float2 v1 = {acc[mi][ni][2] + bi0, acc[mi][ni][3] + bi1};
                *(float2*)(g_H + r0 * NF + f)       = v0;
                *(float2*)(g_H + (r0 + 8) * NF + f) = v1;
            }
        }
        return;
    }

    const int w = (type == 0) ? sub : (2 + sub);
    __half* plane = (type == 0) ? g_out1h : g_out2h;
    const size_t rowbase = (size_t)sub * B_SIZE + b0;

#pragma unroll
    for (int ni = 0; ni < 8; ni++) {
        const int colLocal = warpN + ni * 8 + lc;
        const int f = f0 + colLocal;
        const float bi0 = sbias[colLocal], bi1 = sbias[colLocal + 1];
        float s0 = 0.f, q0 = 0.f, s1 = 0.f, q1 = 0.f;
#pragma unroll
        for (int mi = 0; mi < 4; mi++) {
            const size_t hr0 = (size_t)b0 + warpM + mi * 16 + lr;
            float v00 = acc[mi][ni][0] + bi0;
            float v01 = acc[mi][ni][1] + bi1;
            float v10 = acc[mi][ni][2] + bi0;
            float v11 = acc[mi][ni][3] + bi1;
            if (type == 1) {
                float2 h0 = *(const float2*)(g_H + hr0 * NF + f);
                float2 h1 = *(const float2*)(g_H + (hr0 + 8) * NF + f);
                v00 += h0.x; v01 += h0.y; v10 += h1.x; v11 += h1.y;
            }
            const size_t r0 = rowbase + warpM + mi * 16 + lr;
            *(__half2*)(plane + r0 * NF + f)       = __floats2half2_rn(v00, v01);
            *(__half2*)(plane + (r0 + 8) * NF + f) = __floats2half2_rn(v10, v11);
            s0 += v00 + v10; q0 += v00 * v00 + v10 * v10;
            s1 += v01 + v11; q1 += v01 * v01 + v11 * v11;
        }
#pragma unroll
        for (int off = 4; off < 32; off <<= 1) {
            s0 += __shfl_xor_sync(0xFFFFFFFFu, s0, off);
            q0 += __shfl_xor_sync(0xFFFFFFFFu, q0, off);
            s1 += __shfl_xor_sync(0xFFFFFFFFu, s1, off);
            q1 += __shfl_xor_sync(0xFFFFFFFFu, q1, off);
        }
        if (lane < 4) {
            const int cl = nhalf * 64 + ni * 8 + lane * 2;
            atomicAdd(&sred[cl], s0);       atomicAdd(&sred[128 + cl], q0);
            atomicAdd(&sred[cl + 1], s1);   atomicAdd(&sred[128 + cl + 1], q1);
        }
    }
    __syncthreads();
    atomicAdd(&g_sumf[w * NF + f0 + tid], sred[tid]);
    atomicAdd(&g_sqf [w * NF + f0 + tid], sred[128 + tid]);
}

// ---------------- finalize scale/shift ----------------
__global__ void bn_finalize_kernel(
    const float* __restrict__ g1, const float* __restrict__ be1,
    const float* __restrict__ g2, const float* __restrict__ be2)
{
    int c = blockIdx.x * blockDim.x + threadIdx.x;
    if (c >= NWIN * NF) return;
    int w = c >> 9;
    int f = c & (NF - 1);
    double mean = (double)g_sumf[c] / (double)B_SIZE;
    double var  = (double)g_sqf[c] / (double)B_SIZE - mean * mean;
    float gamma = (w < 2) ? g1[f] : g2[f];
    float beta  = (w < 2) ? be1[f] : be2[f];
    double istd = rsqrt(var + BN_EPS);
    float sc = (float)(gamma * istd);
    g_scale[c] = sc;
    g_shift[c] = beta - (float)(mean * (double)sc);
}

// ---------------- BN + relu + min + fc ----------------
__global__ __launch_bounds__(128) void final_kernel(
    const float* __restrict__ fc_w,
    const float* __restrict__ fc_b,
    float* __restrict__ out)
{
    const int b   = blockIdx.x;
    const int tid = threadIdx.x;
    const int f   = tid * 4;

    const __half2* p0 = (const __half2*)&g_out1h[(size_t)b * NF + f];
    const __half2* p1 = (const __half2*)&g_out1h[((size_t)B_SIZE + b) * NF + f];
    float2 o0a = __half22float2(p0[0]), o0b = __half22float2(p0[1]);
    float2 o1a = __half22float2(p1[0]), o1b = __half22float2(p1[1]);
    float pk[4][4];
#pragma unroll
    for (int k = 0; k < 4; k++) {
        const __half2* pp = (const __half2*)&g_out2h[((size_t)k * B_SIZE + b) * NF + f];
        float2 a = __half22float2(pp[0]), c = __half22float2(pp[1]);
        pk[k][0] = a.x; pk[k][1] = a.y; pk[k][2] = c.x; pk[k][3] = c.y;
    }

    float x0v[4] = {o0a.x, o0a.y, o0b.x, o0b.y};
    float x1v[4] = {o1a.x, o1a.y, o1b.x, o1b.y};

    float acc = 0.f;
#pragma unroll
    for (int l = 0; l < 4; l++) {
        const int fl = f + l;
        float m = fmaxf(0.f, x0v[l] * g_scale[0 * NF + fl] + g_shift[0 * NF + fl]);
        m = fminf(m, fmaxf(0.f, x1v[l] * g_scale[1 * NF + fl] + g_shift[1 * NF + fl]));
#pragma unroll
        for (int k = 0; k < 4; k++)
            m = fminf(m, fmaxf(0.f, pk[k][l] * g_scale[(2 + k) * NF + fl] + g_shift[(2 + k) * NF + fl]));
        acc += fc_w[fl] * m;
    }

    __shared__ float red[4];
#pragma unroll
    for (int o = 16; o > 0; o >>= 1) acc += __shfl_down_sync(0xFFFFFFFFu, acc, o);
    if ((tid & 31) == 0) red[tid >> 5] = acc;
    __syncthreads();
    if (tid == 0) out[b] = red[0] + red[1] + red[2] + red[3] + fc_b[0];
}

// ---------------- launch ----------------
extern "C" void kernel_launch(void* const* d_in, const int* in_sizes, int n_in,
                              void* d_out, int out_size) {
    int o = (in_sizes[1] == 1) ? 1 : 0;  // skip scalar arity if present
    const int*   x      = (const int*)  d_in[0];
    const float* emb_r  = (const float*)d_in[1 + o];
    const float* emb_v  = (const float*)d_in[2 + o];
    const float* w1     = (const float*)d_in[3 + o];
    const float* b1     = (const float*)d_in[4 + o];
    const float* bn1_g  = (const float*)d_in[5 + o];
    const float* bn1_b  = (const float*)d_in[6 + o];
    const float* w2     = (const float*)d_in[7 + o];
    const float* b2     = (const float*)d_in[8 + o];
    const float* bn2_g  = (const float*)d_in[9 + o];
    const float* bn2_b  = (const float*)d_in[10 + o];
    const float* fc_w   = (const float*)d_in[11 + o];
    const float* fc_b   = (const float*)d_in[12 + o];
    float* out = (float*)d_out;

    cudaFuncSetAttribute(gemm_kernel, cudaFuncAttributeMaxDynamicSharedMemorySize, SMEM_TOTAL);

    const int nre = in_sizes[1 + o];  // NR*E
    const int nve = in_sizes[2 + o];  // NV*E

    prep_tables_kernel<<<2048, 256>>>(emb_r, emb_v, nre, nve);
    prep_w_kernel<<<1024, 256>>>(w1, w2);   // also zeroes stats

    // phase 0: typeH -> g_H
    gemm_kernel<<<dim3(256, 4), 128, SMEM_TOTAL>>>(0, x, b2);
    // phase 1: type0/1 -> planes + stats (reads g_H)
    gemm_kernel<<<dim3(1536, 4), 128, SMEM_TOTAL>>>(1, x, b1);

    bn_finalize_kernel<<<(NWIN * NF + 255) / 256, 256>>>(bn1_g, bn1_b, bn2_g, bn2_b);
    final_kernel<<<B_SIZE, 128>>>(fc_w, fc_b, out);
}

// round 17
// speedup vs baseline: 1.3506x; 1.3506x over previous
#include <cuda_runtime.h>
#include <cuda_fp16.h>
#include <math.h>
#include <stdint.h>

#define B_SIZE 32768
#define E_DIM  256
#define NF     512
#define NWIN   6
#define BN_EPS 1e-5
#define KCAT   1792   // 512 (type0) + 512 (type1) + 768 (typeH)
#define NRV    50000

// ---------------- scratch (static device arrays) ----------------
__device__ __half g_out1h[(size_t)2 * B_SIZE * NF];  // windows 0,1 (with bias), fp16
__device__ __half g_Hh   [(size_t)B_SIZE * NF];      // H + b2, fp16
__device__ __half g_out2h[(size_t)4 * B_SIZE * NF];  // windows 2..5 complete (H + p2), fp16
__device__ float  g_sumf[NWIN * NF];
__device__ float  g_sqf [NWIN * NF];
__device__ float  g_scale[NWIN * NF];
__device__ float  g_shift[NWIN * NF];

// fp16 tables / weights
__device__ __half g_er[(size_t)NRV * E_DIM];
__device__ __half g_ev[(size_t)NRV * E_DIM];
__device__ __half g_w_h[(size_t)NF * KCAT];

// ---------------- helpers ----------------
__device__ __forceinline__ uint32_t smem_u32(const void* p) {
    uint32_t a;
    asm("{ .reg .u64 t; cvta.to.shared.u64 t, %1; cvt.u32.u64 %0, t; }" : "=r"(a) : "l"(p));
    return a;
}
__device__ __forceinline__ void cp16(uint32_t dst, const void* src) {
    asm volatile("cp.async.cg.shared.global [%0], [%1], 16;" :: "r"(dst), "l"(src));
}
__device__ __forceinline__ void ldsm4(uint32_t& r0, uint32_t& r1, uint32_t& r2, uint32_t& r3,
                                      uint32_t addr) {
    asm volatile("ldmatrix.sync.aligned.m8n8.x4.shared.b16 {%0,%1,%2,%3}, [%4];"
                 : "=r"(r0), "=r"(r1), "=r"(r2), "=r"(r3) : "r"(addr));
}
__device__ __forceinline__ void mma16816(float* d, const uint32_t* a, uint32_t b0, uint32_t b1) {
    asm volatile(
        "mma.sync.aligned.m16n8k16.row.col.f32.f16.f16.f32 "
        "{%0,%1,%2,%3}, {%4,%5,%6,%7}, {%8,%9}, {%0,%1,%2,%3};"
        : "+f"(d[0]), "+f"(d[1]), "+f"(d[2]), "+f"(d[3])
        : "r"(a[0]), "r"(a[1]), "r"(a[2]), "r"(a[3]), "r"(b0), "r"(b1));
}

// ---------------- prep kernels ----------------
__global__ void prep_tables_kernel(const float* __restrict__ er,
                                   const float* __restrict__ ev,
                                   int nre, int nve) {
    int total = nre + nve;
    for (int i = blockIdx.x * blockDim.x + threadIdx.x; i < total; i += gridDim.x * blockDim.x) {
        if (i < nre) g_er[i] = __float2half_rn(er[i]);
        else         g_ev[i - nre] = __float2half_rn(ev[i - nre]);
    }
}

__global__ void prep_w_kernel(const float* __restrict__ w1, const float* __restrict__ w2) {
    for (int i = blockIdx.x * blockDim.x + threadIdx.x; i < NF * KCAT; i += gridDim.x * blockDim.x) {
        if (i < NWIN * NF) { g_sumf[i] = 0.f; g_sqf[i] = 0.f; }
        int f = i / KCAT, k = i % KCAT;
        float v;
        if      (k < 256)  v = w1[((size_t)f * 2 + 0) * E_DIM + k];
        else if (k < 512)  v = w1[((size_t)f * 2 + 1) * E_DIM + (k - 256)];
        else if (k < 768)  v = w2[((size_t)f * 5 + 3) * E_DIM + (k - 512)];
        else if (k < 1024) v = w2[((size_t)f * 5 + 4) * E_DIM + (k - 768)];
        else if (k < 1280) v = w2[((size_t)f * 5 + 0) * E_DIM + (k - 1024)];
        else if (k < 1536) v = w2[((size_t)f * 5 + 1) * E_DIM + (k - 1280)];
        else               v = w2[((size_t)f * 5 + 2) * E_DIM + (k - 1536)];
        g_w_h[i] = __float2half_rn(v);
    }
}

// ---------------- GEMM kernel (mma.sync fp16, single MMA) ----------------
// phase 0: typeH, grid (256, 4)  -> writes g_Hh (= H + b2, fp16)
// phase 1: type0/1, grid (1536, 4) -> writes g_out1h / g_out2h(+H), computes BN stats
// block 256 (8 warps, 4x2; warp tile 32x64), 2 CTAs/SM.
// smem: [0,512) bias; [512,1536) stats red; 2 stages of 32KB at 4096 (A 16K | B 16K).
// Single barrier per chunk: wait(c) ; sync ; issue(c+1) ; mma(c).
#define SM_RED      512
#define SM_STAGE0   4096
#define STAGE_BYTES 32768
#define SMEM_TOTAL  (SM_STAGE0 + 2 * STAGE_BYTES)

__global__ __launch_bounds__(256, 2) void gemm_kernel(
    const int phase,
    const int* __restrict__ x,
    const float* __restrict__ bvec)
{
    extern __shared__ char smem[];
    const uint32_t sb = smem_u32(smem);
    const int tid = threadIdx.x, wid = tid >> 5, lane = tid & 31;
    const int f0 = blockIdx.y * 128;

    int type, sub, b0, nch, kbase;
    if (phase == 0) { type = 2; sub = 0; b0 = blockIdx.x * 128; nch = 12; kbase = 1024; }
    else {
        const int tile = blockIdx.x;
        if (tile < 512) { type = 0; sub = tile >> 8;         b0 = (tile & 255) * 128;         nch = 8; kbase = 0; }
        else            { type = 1; sub = (tile - 512) >> 8; b0 = ((tile - 512) & 255) * 128; nch = 8; kbase = 512; }
    }

    {
        const float* bp = (type == 1) ? (const float*)0 : bvec;
        float* sbias = (float*)smem;
        if (tid < 128) sbias[tid] = bp ? bp[f0 + tid] : 0.0f;
        float* sred = (float*)(smem + SM_RED);
        if (tid < 256) sred[tid] = 0.0f;
    }

    // ---- gather setup: hoist per-cq index loads ----
    const int row = tid >> 1, half2v = tid & 1;
    const __half* Ath[3];
    int aidx[3] = {0, 0, 0};
    {
        int cols[3] = {0, 0, 0};
        int ncq;
        if (type == 0)      { cols[0] = 2 * sub + 1; Ath[0] = g_ev;
                              cols[1] = 0;           Ath[1] = g_er; ncq = 2; Ath[2] = g_er; }
        else if (type == 1) { cols[0] = 4 + 2 * sub; Ath[0] = g_er;
                              cols[1] = 5 + 2 * sub; Ath[1] = g_ev; ncq = 2; Ath[2] = g_ev; }
        else                { cols[0] = 1; Ath[0] = g_ev;
                              cols[1] = 0; Ath[1] = g_er;
                              cols[2] = 3; Ath[2] = g_ev; ncq = 3; }
        const int* xrow = x + (size_t)(b0 + row) * 12;
#pragma unroll
        for (int q = 0; q < 3; q++)
            if (q < ncq) aidx[q] = __ldg(xrow + cols[q]);
    }

    auto issue_loads = [&](int cc) {
        const uint32_t tb = sb + SM_STAGE0 + (uint32_t)(cc & 1) * STAGE_BYTES;
        const uint32_t ro = (uint32_t)row * 128;
        const uint32_t xr = (uint32_t)(row & 7);
        // A row gather
        {
            const int cq = cc >> 2, e0 = (cc & 3) * 64;
            const char* sh = (const char*)(Ath[cq] + (size_t)aidx[cq] * E_DIM + e0);
#pragma unroll
            for (int g = 0; g < 4; g++) {
                const int gg = half2v * 4 + g;
                const uint32_t so = ro + (uint32_t)((gg ^ xr) * 16);
                cp16(tb + so, sh + gg * 16);
            }
        }
        // B rows (feature f0+row)
        {
            const char* ph = (const char*)(g_w_h + (size_t)(f0 + row) * KCAT + kbase + cc * 64);
#pragma unroll
            for (int g = 0; g < 4; g++) {
                const int gg = half2v * 4 + g;
                const uint32_t so = ro + (uint32_t)((gg ^ xr) * 16);
                cp16(tb + 16384 + so, ph + gg * 16);
            }
        }
        asm volatile("cp.async.commit_group;" ::: "memory");
    };

    // ---- per-warp frag addressing ----
    const int warpM = (wid & 3) * 32;
    const int warpN = (wid >> 2) * 64;
    uint32_t aOff[2], aXor[2];
#pragma unroll
    for (int mi = 0; mi < 2; mi++) {
        const int r = warpM + mi * 16 + (lane & 15);
        aOff[mi] = (uint32_t)r * 128;
        aXor[mi] = (uint32_t)(r & 7);
    }
    const uint32_t aSel = (uint32_t)((lane >> 4) & 1);
    uint32_t bOff[4], bXor[4];
#pragma unroll
    for (int p = 0; p < 4; p++) {
        const int r = warpN + p * 16 + (lane & 7) + (((lane >> 4) & 1) << 3);
        bOff[p] = (uint32_t)r * 128;
        bXor[p] = (uint32_t)(r & 7);
    }
    const uint32_t bSel = (uint32_t)((lane >> 3) & 1);

    float acc[2][8][4];
#pragma unroll
    for (int mi = 0; mi < 2; mi++)
#pragma unroll
        for (int ni = 0; ni < 8; ni++)
#pragma unroll
            for (int q = 0; q < 4; q++) acc[mi][ni][q] = 0.f;

    issue_loads(0);

    for (int c = 0; c < nch; c++) {
        asm volatile("cp.async.wait_group 0;" ::: "memory");
        __syncthreads();                     // chunk c ready; all warps done with c-1
        if (c + 1 < nch) issue_loads(c + 1); // other buffer last read in c-1 — safe

        const uint32_t tb = sb + SM_STAGE0 + (uint32_t)(c & 1) * STAGE_BYTES;
#pragma unroll
        for (int s = 0; s < 4; s++) {
            uint32_t fah[2][4], fb[4][4];
            const uint32_t blk = (uint32_t)(2 * s);
#pragma unroll
            for (int mi = 0; mi < 2; mi++) {
                const uint32_t ad = tb + aOff[mi] + (((blk + aSel) ^ aXor[mi]) * 16);
                ldsm4(fah[mi][0], fah[mi][1], fah[mi][2], fah[mi][3], ad);
            }
#pragma unroll
            for (int p = 0; p < 4; p++) {
                const uint32_t bd = tb + 16384 + bOff[p] + (((blk + bSel) ^ bXor[p]) * 16);
                ldsm4(fb[p][0], fb[p][1], fb[p][2], fb[p][3], bd);
            }
#pragma unroll
            for (int mi = 0; mi < 2; mi++)
#pragma unroll
                for (int ni = 0; ni < 8; ni++) {
                    const int p = ni >> 1, o = (ni & 1) * 2;
                    mma16816(acc[mi][ni], fah[mi], fb[p][o], fb[p][o + 1]);
                }
        }
    }

    // ---- epilogue ----
    const float* sbias = (const float*)smem;
    float* sred = (float*)(smem + SM_RED);
    const int lr = lane >> 2, lc = (lane & 3) * 2;
    const int nhalf = wid >> 2;

    if (type == 2) {
#pragma unroll
        for (int mi = 0; mi < 2; mi++) {
            const size_t r0 = (size_t)b0 + warpM + mi * 16 + lr;
#pragma unroll
            for (int ni = 0; ni < 8; ni++) {
                const int colLocal = warpN + ni * 8 + lc;
                const int f = f0 + colLocal;
                const float bi0 = sbias[colLocal], bi1 = sbias[colLocal + 1];
                *(__half2*)(g_Hh + r0 * NF + f) =
                    __floats2half2_rn(acc[mi][ni][0] + bi0, acc[mi][ni][1] + bi1);
                *(__half2*)(g_Hh + (r0 + 8) * NF + f) =
                    __floats2half2_rn(acc[mi][ni][2] + bi0, acc[mi][ni][3] + bi1);
            }
        }
        return;
    }

    const int w = (type == 0) ? sub : (2 + sub);
    __half* plane = (type == 0) ? g_out1h : g_out2h;
    const size_t rowbase = (size_t)sub * B_SIZE + b0;

#pragma unroll
    for (int ni = 0; ni < 8; ni++) {
        const int colLocal = warpN + ni * 8 + lc;
        const int f = f0 + colLocal;
        const float bi0 = sbias[colLocal], bi1 = sbias[colLocal + 1];
        float s0 = 0.f, q0 = 0.f, s1 = 0.f, q1 = 0.f;
#pragma unroll
        for (int mi = 0; mi < 2; mi++) {
            const size_t hr0 = (size_t)b0 + warpM + mi * 16 + lr;
            float v00 = acc[mi][ni][0] + bi0;
            float v01 = acc[mi][ni][1] + bi1;
            float v10 = acc[mi][ni][2] + bi0;
            float v11 = acc[mi][ni][3] + bi1;
            if (type == 1) {
                float2 h0 = __half22float2(*(const __half2*)(g_Hh + hr0 * NF + f));
                float2 h1 = __half22float2(*(const __half2*)(g_Hh + (hr0 + 8) * NF + f));
                v00 += h0.x; v01 += h0.y; v10 += h1.x; v11 += h1.y;
            }
            const size_t r0 = rowbase + warpM + mi * 16 + lr;
            *(__half2*)(plane + r0 * NF + f)       = __floats2half2_rn(v00, v01);
            *(__half2*)(plane + (r0 + 8) * NF + f) = __floats2half2_rn(v10, v11);
            s0 += v00 + v10; q0 += v00 * v00 + v10 * v10;
            s1 += v01 + v11; q1 += v01 * v01 + v11 * v11;
        }
#pragma unroll
        for (int off = 4; off < 32; off <<= 1) {
            s0 += __shfl_xor_sync(0xFFFFFFFFu, s0, off);
            q0 += __shfl_xor_sync(0xFFFFFFFFu, q0, off);
            s1 += __shfl_xor_sync(0xFFFFFFFFu, s1, off);
            q1 += __shfl_xor_sync(0xFFFFFFFFu, q1, off);
        }
        if (lane < 4) {
            const int cl = nhalf * 64 + ni * 8 + lane * 2;
            atomicAdd(&sred[cl], s0);       atomicAdd(&sred[128 + cl], q0);
            atomicAdd(&sred[cl + 1], s1);   atomicAdd(&sred[128 + cl + 1], q1);
        }
    }
    __syncthreads();
    if (tid < 128)      atomicAdd(&g_sumf[w * NF + f0 + tid], sred[tid]);
    else if (tid < 256) atomicAdd(&g_sqf [w * NF + f0 + (tid - 128)], sred[tid]);
}

// ---------------- finalize scale/shift ----------------
__global__ void bn_finalize_kernel(
    const float* __restrict__ g1, const float* __restrict__ be1,
    const float* __restrict__ g2, const float* __restrict__ be2)
{
    int c = blockIdx.x * blockDim.x + threadIdx.x;
    if (c >= NWIN * NF) return;
    int w = c >> 9;
    int f = c & (NF - 1);
    double mean = (double)g_sumf[c] / (double)B_SIZE;
    double var  = (double)g_sqf[c] / (double)B_SIZE - mean * mean;
    float gamma = (w < 2) ? g1[f] : g2[f];
    float beta  = (w < 2) ? be1[f] : be2[f];
    double istd = rsqrt(var + BN_EPS);
    float sc = (float)(gamma * istd);
    g_scale[c] = sc;
    g_shift[c] = beta - (float)(mean * (double)sc);
}

// ---------------- BN + relu + min + fc ----------------
__global__ __launch_bounds__(128) void final_kernel(
    const float* __restrict__ fc_w,
    const float* __restrict__ fc_b,
    float* __restrict__ out)
{
    const int b   = blockIdx.x;
    const int tid = threadIdx.x;
    const int f   = tid * 4;

    const __half2* p0 = (const __half2*)&g_out1h[(size_t)b * NF + f];
    const __half2* p1 = (const __half2*)&g_out1h[((size_t)B_SIZE + b) * NF + f];
    float2 o0a = __half22float2(p0[0]), o0b = __half22float2(p0[1]);
    float2 o1a = __half22float2(p1[0]), o1b = __half22float2(p1[1]);
    float pk[4][4];
#pragma unroll
    for (int k = 0; k < 4; k++) {
        const __half2* pp = (const __half2*)&g_out2h[((size_t)k * B_SIZE + b) * NF + f];
        float2 a = __half22float2(pp[0]), c = __half22float2(pp[1]);
        pk[k][0] = a.x; pk[k][1] = a.y; pk[k][2] = c.x; pk[k][3] = c.y;
    }

    float x0v[4] = {o0a.x, o0a.y, o0b.x, o0b.y};
    float x1v[4] = {o1a.x, o1a.y, o1b.x, o1b.y};

    float acc = 0.f;
#pragma unroll
    for (int l = 0; l < 4; l++) {
        const int fl = f + l;
        float m = fmaxf(0.f, x0v[l] * g_scale[0 * NF + fl] + g_shift[0 * NF + fl]);
        m = fminf(m, fmaxf(0.f, x1v[l] * g_scale[1 * NF + fl] + g_shift[1 * NF + fl]));
#pragma unroll
        for (int k = 0; k < 4; k++)
            m = fminf(m, fmaxf(0.f, pk[k][l] * g_scale[(2 + k) * NF + fl] + g_shift[(2 + k) * NF + fl]));
        acc += fc_w[fl] * m;
    }

    __shared__ float red[4];
#pragma unroll
    for (int o = 16; o > 0; o >>= 1) acc += __shfl_down_sync(0xFFFFFFFFu, acc, o);
    if ((tid & 31) == 0) red[tid >> 5] = acc;
    __syncthreads();
    if (tid == 0) out[b] = red[0] + red[1] + red[2] + red[3] + fc_b[0];
}

// ---------------- launch ----------------
extern "C" void kernel_launch(void* const* d_in, const int* in_sizes, int n_in,
                              void* d_out, int out_size) {
    int o = (in_sizes[1] == 1) ? 1 : 0;  // skip scalar arity if present
    const int*   x      = (const int*)  d_in[0];
    const float* emb_r  = (const float*)d_in[1 + o];
    const float* emb_v  = (const float*)d_in[2 + o];
    const float* w1     = (const float*)d_in[3 + o];
    const float* b1     = (const float*)d_in[4 + o];
    const float* bn1_g  = (const float*)d_in[5 + o];
    const float* bn1_b  = (const float*)d_in[6 + o];
    const float* w2     = (const float*)d_in[7 + o];
    const float* b2     = (const float*)d_in[8 + o];
    const float* bn2_g  = (const float*)d_in[9 + o];
    const float* bn2_b  = (const float*)d_in[10 + o];
    const float* fc_w   = (const float*)d_in[11 + o];
    const float* fc_b   = (const float*)d_in[12 + o];
    float* out = (float*)d_out;

    cudaFuncSetAttribute(gemm_kernel, cudaFuncAttributeMaxDynamicSharedMemorySize, SMEM_TOTAL);

    const int nre = in_sizes[1 + o];  // NR*E
    const int nve = in_sizes[2 + o];  // NV*E

    prep_tables_kernel<<<2048, 256>>>(emb_r, emb_v, nre, nve);
    prep_w_kernel<<<1024, 256>>>(w1, w2);   // also zeroes stats

    // phase 0: typeH -> g_Hh
    gemm_kernel<<<dim3(256, 4), 256, SMEM_TOTAL>>>(0, x, b2);
    // phase 1: type0/1 -> planes + stats (reads g_Hh)
    gemm_kernel<<<dim3(1536, 4), 256, SMEM_TOTAL>>>(1, x, b1);

    bn_finalize_kernel<<<(NWIN * NF + 255) / 256, 256>>>(bn1_g, bn1_b, bn2_g, bn2_b);
    final_kernel<<<B_SIZE, 128>>>(fc_w, fc_b, out);
}